// round 4
// baseline (speedup 1.0000x reference)
#include <cuda_runtime.h>
#include <cstdint>
#include <cstddef>

// ---------------- problem constants ----------------
#define TOTAL_TILES  8192            // 1048576 / 128
#define NSTAGE       4
#define AROWSTRIDE   68              // floats: 64 data + 4 pad (stride % 32 == 4 -> conflict-free)
#define STAGE_FLOATS (128 * AROWSTRIDE)          // 8704 floats = 34816 B
#define WSTRIDE      264             // floats: 256 data + 8 pad (stride % 32 == 8 -> conflict-free v2)
#define SW_OFF       (NSTAGE * STAGE_FLOATS)     // 34816 floats
#define SMEM_FLOATS  (SW_OFF + 64 * WSTRIDE)     // 51712 floats
#define SMEM_BYTES   (SMEM_FLOATS * 4)           // 206848 B

// ---------------- helpers ----------------
__device__ __forceinline__ uint32_t smem_u32(const void* p) {
    uint32_t a;
    asm("{ .reg .u64 t; cvta.to.shared.u64 t, %1; cvt.u32.u64 %0, t; }"
        : "=r"(a) : "l"(p));
    return a;
}

__device__ __forceinline__ uint32_t f2tf32(float f) {
    uint32_t r;
    asm("cvt.rna.tf32.f32 %0, %1;" : "=r"(r) : "f"(f));
    return r;
}

__device__ __forceinline__ void cpa16(uint32_t dst, const void* src) {
    asm volatile("cp.async.cg.shared.global [%0], [%1], 16;"
                 :: "r"(dst), "l"(src) : "memory");
}
#define CPA_COMMIT() asm volatile("cp.async.commit_group;" ::: "memory")
#define CPA_WAIT(n)  asm volatile("cp.async.wait_group %0;" :: "n"(n) : "memory")

__device__ __forceinline__ void mma_tf32(float* c, const uint32_t* a, const uint32_t* b) {
    asm("mma.sync.aligned.m16n8k8.row.col.f32.tf32.tf32.f32 "
        "{%0,%1,%2,%3}, {%4,%5,%6,%7}, {%8,%9}, {%0,%1,%2,%3};"
        : "+f"(c[0]), "+f"(c[1]), "+f"(c[2]), "+f"(c[3])
        : "r"(a[0]), "r"(a[1]), "r"(a[2]), "r"(a[3]), "r"(b[0]), "r"(b[1]));
}

// ---------------- kernel ----------------
__global__ void __launch_bounds__(256, 1)
NN_38010460570161_kernel(const float* __restrict__ X,
                         const float* __restrict__ W,
                         float* __restrict__ O)
{
    extern __shared__ float smem[];
    float* sA = smem;            // [NSTAGE][128][AROWSTRIDE]
    float* sW = smem + SW_OFF;   // [64][WSTRIDE], fragment-permuted + tf32-converted

    const int tid  = threadIdx.x;
    const int lane = tid & 31;
    const int wid  = tid >> 5;

    // ---- W: load once, convert to tf32 (RNA), permute cols so (k, k+4) pairs
    // are adjacent: old col 8g+4j+c  ->  new col 8g+2c+j ----
    for (int idx = tid; idx < 64 * 256; idx += 256) {
        const int n = idx >> 8, k = idx & 255;
        const int g = k >> 3, r = k & 7, j = r >> 2, c = r & 3;
        sW[n * WSTRIDE + (g << 3) + (c << 1) + j] =
            __uint_as_float(f2tf32(W[idx]));
    }

    const int cta  = blockIdx.x;
    const int ncta = gridDim.x;
    const int ntiles  = (TOTAL_TILES - cta + ncta - 1) / ncta;
    const int nchunks = ntiles * 4;          // chunk = 128 rows x 64 K-floats (32 KB)

    const uint32_t sAb = smem_u32(sA);

    auto issue = [&](int g) {
        const int tile = cta + (g >> 2) * ncta;
        const int ck   = g & 3;
        const uint32_t stage = sAb + (uint32_t)((g & (NSTAGE - 1)) * STAGE_FLOATS) * 4u;
        const float* src0 = X + (size_t)tile * 128 * 256 + ck * 64;
        #pragma unroll
        for (int it = 0; it < 8; ++it) {
            const int i   = tid + it * 256;
            const int row = i >> 4, j = i & 15;
            cpa16(stage + (uint32_t)(row * AROWSTRIDE + j * 4) * 4u,
                  src0 + (size_t)row * 256 + j * 4);
        }
        CPA_COMMIT();
    };

    // prologue: 3 chunks in flight
    issue(0); issue(1); issue(2);

    const int rowbase = (wid & 3) * 32;     // M split across 4 warps
    const int colbase = (wid >> 2) * 32;    // N split across 2 warps
    const int q  = lane >> 2;               // groupID 0..7
    const int t4 = lane & 3;                // threadID_in_group

    float acc[2][4][4];

    for (int g = 0; g < nchunks; ++g) {
        const int ck = g & 3;
        if (ck == 0) {
            #pragma unroll
            for (int mi = 0; mi < 2; ++mi)
                #pragma unroll
                for (int ni = 0; ni < 4; ++ni)
                    #pragma unroll
                    for (int v = 0; v < 4; ++v) acc[mi][ni][v] = 0.0f;
        }

        CPA_WAIT(2);
        __syncthreads();   // cp.async writes + (first iter) sW writes visible

        const float* stg = sA + (g & (NSTAGE - 1)) * STAGE_FLOATS;

        #pragma unroll
        for (int kk = 0; kk < 8; ++kk) {            // 8 k-steps of K=8
            const int k0 = kk * 8;

            uint32_t a[2][4];
            #pragma unroll
            for (int mi = 0; mi < 2; ++mi) {
                const float* ap = stg + (rowbase + mi * 16 + q) * AROWSTRIDE + k0 + t4;
                a[mi][0] = f2tf32(ap[0]);                    // (r,   c)
                a[mi][1] = f2tf32(ap[8 * AROWSTRIDE]);       // (r+8, c)
                a[mi][2] = f2tf32(ap[4]);                    // (r,   c+4)
                a[mi][3] = f2tf32(ap[8 * AROWSTRIDE + 4]);   // (r+8, c+4)
            }

            const int kg = ck * 64 + k0 + (t4 << 1);  // permuted: (k, k+4) adjacent
            uint32_t b[4][2];
            #pragma unroll
            for (int ni = 0; ni < 4; ++ni) {
                const float2 bv =
                    *(const float2*)(sW + (colbase + ni * 8 + q) * WSTRIDE + kg);
                b[ni][0] = __float_as_uint(bv.x);
                b[ni][1] = __float_as_uint(bv.y);
            }

            #pragma unroll
            for (int mi = 0; mi < 2; ++mi)
                #pragma unroll
                for (int ni = 0; ni < 4; ++ni)
                    mma_tf32(acc[mi][ni], a[mi], b[ni]);
        }

        __syncthreads();   // all warps done reading stage (g-1)%4 gets recycled next
        if (g + 3 < nchunks) issue(g + 3);
        else                 CPA_COMMIT();   // empty group keeps wait_group math valid

        if (ck == 3) {
            // epilogue for finished tile; overlaps with in-flight cp.async
            const int tile = cta + (g >> 2) * ncta;
            #pragma unroll
            for (int mi = 0; mi < 2; ++mi) {
                const size_t row0 = (size_t)tile * 128 + rowbase + mi * 16 + q;
                #pragma unroll
                for (int ni = 0; ni < 4; ++ni) {
                    const int col = colbase + ni * 8 + (t4 << 1);
                    *(float2*)(O + row0 * 64 + col) =
                        make_float2(acc[mi][ni][0], acc[mi][ni][1]);
                    *(float2*)(O + (row0 + 8) * 64 + col) =
                        make_float2(acc[mi][ni][2], acc[mi][ni][3]);
                }
            }
        }
    }
}

// ---------------- launch ----------------
extern "C" void kernel_launch(void* const* d_in, const int* in_sizes, int n_in,
                              void* d_out, int out_size) {
    const float* X = (const float*)d_in[0];   // [1048576, 256] fp32
    const float* W = (const float*)d_in[1];   // [64, 256] fp32
    float*       O = (float*)d_out;           // [1048576, 64] fp32

    int dev = 0;
    cudaGetDevice(&dev);
    int nsm = 148;
    cudaDeviceGetAttribute(&nsm, cudaDevAttrMultiProcessorCount, dev);
    if (nsm <= 0) nsm = 148;

    cudaFuncSetAttribute(NN_38010460570161_kernel,
                         cudaFuncAttributeMaxDynamicSharedMemorySize, SMEM_BYTES);

    NN_38010460570161_kernel<<<nsm, 256, SMEM_BYTES>>>(X, W, O);
}

// round 5
// speedup vs baseline: 1.2554x; 1.2554x over previous
#include <cuda_runtime.h>
#include <cstdint>
#include <cstddef>

// ---------------- problem constants ----------------
#define TOTAL_TILES  4096            // 1048576 / 256 (M-tile = 256 rows per CTA)
#define NSTAGE       4               // per-warp ring depth
#define AROWSTRIDE   36              // floats: 32 data + 4 pad (lane bank = 4q+t4 -> conflict-free)
#define STAGE_FLOATS (32 * AROWSTRIDE)               // 1152 floats = 4608 B
#define WSTRIDE      264             // floats: 256 data + 8 pad
#define SW_OFF       (8 * NSTAGE * STAGE_FLOATS)     // 36864 floats
#define SMEM_FLOATS  (SW_OFF + 64 * WSTRIDE)         // 53760 floats
#define SMEM_BYTES   (SMEM_FLOATS * 4)               // 215040 B

// ---------------- helpers ----------------
__device__ __forceinline__ uint32_t smem_u32(const void* p) {
    uint32_t a;
    asm("{ .reg .u64 t; cvta.to.shared.u64 t, %1; cvt.u32.u64 %0, t; }"
        : "=r"(a) : "l"(p));
    return a;
}

__device__ __forceinline__ uint32_t f2tf32(float f) {
    uint32_t r;
    asm("cvt.rna.tf32.f32 %0, %1;" : "=r"(r) : "f"(f));
    return r;
}

__device__ __forceinline__ void cpa16(uint32_t dst, const void* src) {
    asm volatile("cp.async.cg.shared.global [%0], [%1], 16;"
                 :: "r"(dst), "l"(src) : "memory");
}
#define CPA_COMMIT() asm volatile("cp.async.commit_group;" ::: "memory")
#define CPA_WAIT(n)  asm volatile("cp.async.wait_group %0;" :: "n"(n) : "memory")

__device__ __forceinline__ void mma_tf32(float* c, const uint32_t* a, const uint32_t* b) {
    asm("mma.sync.aligned.m16n8k8.row.col.f32.tf32.tf32.f32 "
        "{%0,%1,%2,%3}, {%4,%5,%6,%7}, {%8,%9}, {%0,%1,%2,%3};"
        : "+f"(c[0]), "+f"(c[1]), "+f"(c[2]), "+f"(c[3])
        : "r"(a[0]), "r"(a[1]), "r"(a[2]), "r"(a[3]), "r"(b[0]), "r"(b[1]));
}

// ---------------- kernel ----------------
__global__ void __launch_bounds__(256, 1)
NN_38010460570161_kernel(const float* __restrict__ X,
                         const float* __restrict__ W,
                         float* __restrict__ O)
{
    extern __shared__ float smem[];
    float* sA = smem;            // [8 warps][NSTAGE][32][AROWSTRIDE]
    float* sW = smem + SW_OFF;   // [64][WSTRIDE], fragment-permuted + tf32

    const int tid  = threadIdx.x;
    const int lane = tid & 31;
    const int wid  = tid >> 5;

    // ---- W: load once, tf32 (RNA), permute cols so (k, k+4) pairs adjacent:
    // old col 8g+4j+c -> new col 8g+2c+j ----
    for (int idx = tid; idx < 64 * 256; idx += 256) {
        const int n = idx >> 8, k = idx & 255;
        const int g = k >> 3, r = k & 7, j = r >> 2, c = r & 3;
        sW[n * WSTRIDE + (g << 3) + (c << 1) + j] =
            __uint_as_float(f2tf32(W[idx]));
    }
    __syncthreads();   // the ONLY CTA barrier

    const int cta  = blockIdx.x;
    const int ncta = gridDim.x;
    const int ntiles  = (TOTAL_TILES - cta + ncta - 1) / ncta;
    const int nchunks = ntiles * 8;     // chunk = 32 rows x 32 K-floats (4 KB) per warp

    float* stg0 = sA + wid * (NSTAGE * STAGE_FLOATS);
    const uint32_t stg0_u = smem_u32(stg0);

    const int r0  = lane >> 3;          // 0..3   (cp.async row group)
    const int seg = lane & 7;           // 16B segment within 128B row

    auto issue = [&](int g) {
        const int ck = g & 7;
        const long long tile = cta + (long long)(g >> 3) * ncta;
        const float* src = X + ((size_t)tile * 256 + wid * 32) * 256 + ck * 32;
        const uint32_t dst = stg0_u + (uint32_t)((g & (NSTAGE - 1)) * STAGE_FLOATS) * 4u;
        #pragma unroll
        for (int j = 0; j < 8; ++j) {
            const int row = r0 + j * 4;
            cpa16(dst + (uint32_t)(row * AROWSTRIDE + seg * 4) * 4u,
                  src + (size_t)row * 256 + seg * 4);
        }
        CPA_COMMIT();
    };

    // prologue: 3 chunks in flight (per warp)
    issue(0); issue(1); issue(2);

    const int q  = lane >> 2;           // groupID 0..7
    const int t4 = lane & 3;            // threadID_in_group

    float acc[2][8][4];

    for (int g = 0; g < nchunks; ++g) {
        const int ck = g & 7;
        if (ck == 0) {
            #pragma unroll
            for (int mi = 0; mi < 2; ++mi)
                #pragma unroll
                for (int ni = 0; ni < 8; ++ni)
                    #pragma unroll
                    for (int v = 0; v < 4; ++v) acc[mi][ni][v] = 0.0f;
        }

        CPA_WAIT(2);
        __syncwarp();   // all lanes' chunk-g copies done + intra-warp visibility

        // refill freed stage (g-1)&3 before computing: +1 chunk of lookahead
        if (g + 3 < nchunks) issue(g + 3);
        else                 CPA_COMMIT();   // empty group keeps wait math valid

        const float* stg = stg0 + (g & (NSTAGE - 1)) * STAGE_FLOATS;

        #pragma unroll
        for (int kk = 0; kk < 4; ++kk) {        // 4 k-steps of K=8
            const int k0 = kk * 8;

            uint32_t a[2][4];
            #pragma unroll
            for (int mi = 0; mi < 2; ++mi) {
                const float* ap = stg + (mi * 16 + q) * AROWSTRIDE + k0 + t4;
                a[mi][0] = f2tf32(ap[0]);                    // (q,    c)
                a[mi][1] = f2tf32(ap[8 * AROWSTRIDE]);       // (q+8,  c)
                a[mi][2] = f2tf32(ap[4]);                    // (q,    c+4)
                a[mi][3] = f2tf32(ap[8 * AROWSTRIDE + 4]);   // (q+8,  c+4)
            }

            const int kg = (ck * 4 + kk) * 8 + (t4 << 1);    // permuted pair
            uint32_t b[8][2];
            #pragma unroll
            for (int ni = 0; ni < 8; ++ni) {
                const float2 bv =
                    *(const float2*)(sW + (ni * 8 + q) * WSTRIDE + kg);
                b[ni][0] = __float_as_uint(bv.x);
                b[ni][1] = __float_as_uint(bv.y);
            }

            #pragma unroll
            for (int mi = 0; mi < 2; ++mi)
                #pragma unroll
                for (int ni = 0; ni < 8; ++ni)
                    mma_tf32(acc[mi][ni], a[mi], b[ni]);
        }

        if (ck == 7) {
            // per-warp epilogue; overlaps other warps' loads/compute
            const long long tile = cta + (long long)(g >> 3) * ncta;
            #pragma unroll
            for (int mi = 0; mi < 2; ++mi) {
                const size_t row0 = (size_t)tile * 256 + wid * 32 + mi * 16 + q;
                #pragma unroll
                for (int ni = 0; ni < 8; ++ni) {
                    const int col = ni * 8 + (t4 << 1);
                    *(float2*)(O + row0 * 64 + col) =
                        make_float2(acc[mi][ni][0], acc[mi][ni][1]);
                    *(float2*)(O + (row0 + 8) * 64 + col) =
                        make_float2(acc[mi][ni][2], acc[mi][ni][3]);
                }
            }
        }
    }
}

// ---------------- launch ----------------
extern "C" void kernel_launch(void* const* d_in, const int* in_sizes, int n_in,
                              void* d_out, int out_size) {
    const float* X = (const float*)d_in[0];   // [1048576, 256] fp32
    const float* W = (const float*)d_in[1];   // [64, 256] fp32
    float*       O = (float*)d_out;           // [1048576, 64] fp32

    int dev = 0;
    cudaGetDevice(&dev);
    int nsm = 148;
    cudaDeviceGetAttribute(&nsm, cudaDevAttrMultiProcessorCount, dev);
    if (nsm <= 0) nsm = 148;

    cudaFuncSetAttribute(NN_38010460570161_kernel,
                         cudaFuncAttributeMaxDynamicSharedMemorySize, SMEM_BYTES);

    NN_38010460570161_kernel<<<nsm, 256, SMEM_BYTES>>>(X, W, O);
}